// round 6
// baseline (speedup 1.0000x reference)
#include <cuda_runtime.h>
#include <cstdint>

#define N_NODES 100000
#define N_EDGES 50000
#define C 128
#define NNZ 1600000

// Scratch (allocation-free): degrees, inverse degrees, softmax weights.
__device__ int   g_deg_v[N_NODES];
__device__ int   g_deg_e[N_EDGES];
__device__ float g_inv_v[N_NODES];
__device__ float g_inv_e[N_EDGES];
__device__ __align__(16) float g_sw0[C];
__device__ __align__(16) float g_sw1[C];

// ---------------------------------------------------------------------------
// Fire-and-forget vector reduction (sm_90+): 1 REDG.128 instead of 4 atomicAdds.
__device__ __forceinline__ void red_add_v4(float* addr, float4 v) {
    asm volatile("red.global.add.v4.f32 [%0], {%1,%2,%3,%4};"
                 :: "l"(addr), "f"(v.x), "f"(v.y), "f"(v.z), "f"(v.w)
                 : "memory");
}

// ---------------------------------------------------------------------------
__global__ void k_zero(float4* __restrict__ out4, int n4) {
    int i = blockIdx.x * blockDim.x + threadIdx.x;
    int stride = gridDim.x * blockDim.x;
    float4 z = make_float4(0.f, 0.f, 0.f, 0.f);
    for (; i < n4; i += stride) out4[i] = z;
}

__global__ void k_zero_deg() {
    int i = blockIdx.x * blockDim.x + threadIdx.x;
    if (i < N_NODES) g_deg_v[i] = 0;
    if (i < N_EDGES) g_deg_e[i] = 0;
}

__global__ void k_softmax(const float* __restrict__ lw) {
    int c = threadIdx.x;  // C threads
    float w0 = lw[c], w1 = lw[C + c];
    float m = fmaxf(w0, w1);
    float e0 = expf(w0 - m), e1 = expf(w1 - m);
    float inv = 1.0f / (e0 + e1);
    g_sw0[c] = e0 * inv;
    g_sw1[c] = e1 * inv;
}

__global__ void k_degrees(const int* __restrict__ nidx,
                          const int* __restrict__ eidx) {
    int i = blockIdx.x * blockDim.x + threadIdx.x;
    if (i < NNZ) {
        atomicAdd(&g_deg_v[__ldg(&nidx[i])], 1);
        atomicAdd(&g_deg_e[__ldg(&eidx[i])], 1);
    }
}

__global__ void k_invert() {
    int i = blockIdx.x * blockDim.x + threadIdx.x;
    if (i < N_NODES) {
        int d = g_deg_v[i];
        g_inv_v[i] = (d > 0) ? (1.0f / (float)d) : 0.0f;
    }
    if (i < N_EDGES) {
        int d = g_deg_e[i];
        g_inv_e[i] = (d > 0) ? (1.0f / (float)d) : 0.0f;
    }
}

// ---------------------------------------------------------------------------
// v2e: edge_acc[edge] += X[node] * inv_deg_v[node]   (warp per incidence)
__global__ void k_v2e(const float* __restrict__ X,
                      const int* __restrict__ nidx,
                      const int* __restrict__ eidx,
                      float* __restrict__ edge_acc) {
    int w = (blockIdx.x * blockDim.x + threadIdx.x) >> 5;
    int lane = threadIdx.x & 31;
    if (w >= NNZ) return;
    int node = 0, edge = 0;
    float s = 0.f;
    if (lane == 0) {
        node = __ldg(&nidx[w]);
        edge = __ldg(&eidx[w]);
        s = __ldg(&g_inv_v[node]);
    }
    node = __shfl_sync(0xFFFFFFFFu, node, 0);
    edge = __shfl_sync(0xFFFFFFFFu, edge, 0);
    s    = __shfl_sync(0xFFFFFFFFu, s, 0);
    float4 v = __ldg(reinterpret_cast<const float4*>(X + (size_t)node * C) + lane);
    v.x *= s; v.y *= s; v.z *= s; v.w *= s;
    red_add_v4(edge_acc + (size_t)edge * C + lane * 4, v);
}

// edge_feat = sw0 * edge_acc + sw1 * Y   (in place over edge_acc)
__global__ void k_edge_mix(float4* __restrict__ acc4, const float4* __restrict__ Y4) {
    int i = blockIdx.x * blockDim.x + threadIdx.x;
    if (i >= N_EDGES * C / 4) return;
    int c4 = i & (C / 4 - 1);  // chunk within row (C/4 = 32)
    float4 s0 = reinterpret_cast<const float4*>(g_sw0)[c4];
    float4 s1 = reinterpret_cast<const float4*>(g_sw1)[c4];
    float4 a = acc4[i];
    float4 y = __ldg(&Y4[i]);
    a.x = s0.x * a.x + s1.x * y.x;
    a.y = s0.y * a.y + s1.y * y.y;
    a.z = s0.z * a.z + s1.z * y.z;
    a.w = s0.w * a.w + s1.w * y.w;
    acc4[i] = a;
}

// e2v: node_acc[node] += edge_feat[edge] * inv_deg_e[edge]
__global__ void k_e2v(const float* __restrict__ edge_feat,
                      const int* __restrict__ nidx,
                      const int* __restrict__ eidx,
                      float* __restrict__ node_acc) {
    int w = (blockIdx.x * blockDim.x + threadIdx.x) >> 5;
    int lane = threadIdx.x & 31;
    if (w >= NNZ) return;
    int node = 0, edge = 0;
    float s = 0.f;
    if (lane == 0) {
        node = __ldg(&nidx[w]);
        edge = __ldg(&eidx[w]);
        s = __ldg(&g_inv_e[edge]);
    }
    node = __shfl_sync(0xFFFFFFFFu, node, 0);
    edge = __shfl_sync(0xFFFFFFFFu, edge, 0);
    s    = __shfl_sync(0xFFFFFFFFu, s, 0);
    float4 v = __ldg(reinterpret_cast<const float4*>(edge_feat + (size_t)edge * C) + lane);
    v.x *= s; v.y *= s; v.z *= s; v.w *= s;
    red_add_v4(node_acc + (size_t)node * C + lane * 4, v);
}

// node_feat = sw0 * node_acc + sw1 * X   (in place over node_acc)
__global__ void k_node_mix(float4* __restrict__ acc4, const float4* __restrict__ X4) {
    int i = blockIdx.x * blockDim.x + threadIdx.x;
    if (i >= N_NODES * C / 4) return;
    int c4 = i & (C / 4 - 1);
    float4 s0 = reinterpret_cast<const float4*>(g_sw0)[c4];
    float4 s1 = reinterpret_cast<const float4*>(g_sw1)[c4];
    float4 a = acc4[i];
    float4 x = __ldg(&X4[i]);
    a.x = s0.x * a.x + s1.x * x.x;
    a.y = s0.y * a.y + s1.y * x.y;
    a.z = s0.z * a.z + s1.z * x.z;
    a.w = s0.w * a.w + s1.w * x.w;
    acc4[i] = a;
}

// ---------------------------------------------------------------------------
extern "C" void kernel_launch(void* const* d_in, const int* in_sizes, int n_in,
                              void* d_out, int out_size) {
    const float* X    = (const float*)d_in[0];  // [N, C]
    const float* Y    = (const float*)d_in[1];  // [E, C]
    const float* lw   = (const float*)d_in[2];  // [2, C]
    const int*   nidx = (const int*)d_in[3];    // [NNZ]  (JAX demotes int64->int32)
    const int*   eidx = (const int*)d_in[4];    // [NNZ]

    float* node_out = (float*)d_out;                   // [N, C]
    float* edge_out = node_out + (size_t)N_NODES * C;  // [E, C]

    const int total4 = (N_NODES + N_EDGES) * C / 4;  // 4.8M float4

    k_zero<<<2048, 256>>>((float4*)d_out, total4);
    k_zero_deg<<<(N_NODES + 255) / 256, 256>>>();
    k_softmax<<<1, C>>>(lw);
    k_degrees<<<(NNZ + 255) / 256, 256>>>(nidx, eidx);
    k_invert<<<(N_NODES + 255) / 256, 256>>>();

    // v2e scatter: one warp per incidence -> 200000 blocks of 8 warps
    k_v2e<<<NNZ / 8, 256>>>(X, nidx, eidx, edge_out);
    k_edge_mix<<<(N_EDGES * C / 4 + 255) / 256, 256>>>((float4*)edge_out, (const float4*)Y);
    k_e2v<<<NNZ / 8, 256>>>(edge_out, nidx, eidx, node_out);
    k_node_mix<<<(N_NODES * C / 4 + 255) / 256, 256>>>((float4*)node_out, (const float4*)X);
}